// round 9
// baseline (speedup 1.0000x reference)
#include <cuda_runtime.h>

// Fixed problem shape: B=8, H=W=512, C=32, n_segments=256
#define B_    8
#define HW_   (512 * 512)
#define C_    32
#define S_    256
#define CPB_  37                  // CTAs per batch
#define NCTA  (B_ * CPB_)         // 296 = 2 x 148 SMs -> one balanced wave
#define TPB   512
#define WARPS 16
#define SEGW  (S_ / WARPS)        // 16 segments owned per warp
#define BP    128                 // pixels per staged block (16 KB image data)
#define UPB   (HW_ / BP)          // 2048 copy units per batch

// Per-CTA partials (float2: .x = sum, .y = count). Fully overwritten each
// launch -> no zeroing, replay-safe, zero atomics -> deterministic.
__device__ float2 g_part[(size_t)NCTA * S_ * C_];   // ~19.4 MB

__device__ __forceinline__ unsigned smem_u32(const void* p) {
    return (unsigned)__cvta_generic_to_shared(p);
}
__device__ __forceinline__ void cp16(unsigned dst, const void* src) {
    asm volatile("cp.async.cg.shared.global [%0], [%1], 16;" :: "r"(dst), "l"(src));
}

// ---------------------------------------------------------------------------
// k_accum: 512 threads (16 warps -> 8/SMSP at 2 CTA/SM) streaming the image
// sequentially via double-buffered cp.async, accumulating into warp-private
// float2 smem bins (sum+count fused -> 3 smem ops per pixel, no atomics).
// smem: bins 64KB + 2 x (16KB img + 512B ids) = ~99 KB -> 2 CTAs/SM.
// Each CTA's unit range lies entirely within one batch (CPB_ CTAs per batch).
// ---------------------------------------------------------------------------
__global__ void __launch_bounds__(TPB, 2) k_accum(const float* __restrict__ img,
                                                  const int* __restrict__ slic) {
    extern __shared__ char smem[];
    float2* s_bin = (float2*)smem;                            // [256][32] f32x2, 64 KB
    float*  s_buf = (float*)(smem + 65536);                   // [2][128][32] f32, 32 KB
    int*    s_ids = (int*)(smem + 65536 + 32768);             // [2][128] i32, 1 KB

    const int tid = threadIdx.x, w = tid >> 5, lane = tid & 31;
    const int lo = w * SEGW;

    #pragma unroll
    for (int i = tid; i < S_ * C_; i += TPB) s_bin[i] = make_float2(0.f, 0.f);

    // Per-batch contiguous unit range (55 or 56 units), never straddles batch.
    const int batch = blockIdx.x / CPB_;
    const int c     = blockIdx.x % CPB_;
    const int u0 = batch * UPB + (c * UPB) / CPB_;
    const int u1 = batch * UPB + ((c + 1) * UPB) / CPB_;
    const int nb = u1 - u0;

    // Prefetch unit u0 into stage 0.
    {
        const char* src = (const char*)(img + (size_t)u0 * BP * C_);
        unsigned d = smem_u32(s_buf);
        cp16(d + (unsigned)tid * 16,         src + (size_t)tid * 16);
        cp16(d + (unsigned)(tid + TPB) * 16, src + (size_t)(tid + TPB) * 16);
        if (tid < 32)
            cp16(smem_u32(s_ids) + tid * 16, (const char*)(slic + (size_t)u0 * BP) + tid * 16);
        asm volatile("cp.async.commit_group;");
    }

    float2* wbin = s_bin + lo * C_;

    for (int g = 0; g < nb; g++) {
        const int cur = g & 1;
        if (g + 1 < nb) {
            const int nxt = cur ^ 1;
            const size_t u = (size_t)(u0 + g + 1) * BP;
            const char* src = (const char*)(img + u * C_);
            unsigned d = smem_u32(s_buf + nxt * BP * C_);
            cp16(d + (unsigned)tid * 16,         src + (size_t)tid * 16);
            cp16(d + (unsigned)(tid + TPB) * 16, src + (size_t)(tid + TPB) * 16);
            if (tid < 32)
                cp16(smem_u32(s_ids + nxt * BP) + tid * 16,
                     (const char*)(slic + u) + tid * 16);
            asm volatile("cp.async.commit_group;");
            asm volatile("cp.async.wait_group 1;");   // in-order retire -> stage cur ready
        } else {
            asm volatile("cp.async.wait_group 0;");
        }
        __syncthreads();

        const float* buf = s_buf + cur * BP * C_;
        const int*   ids = s_ids + cur * BP;

        #pragma unroll
        for (int t = 0; t < BP / 32; t++) {
            int id = ids[t * 32 + lane] - 1;               // 1-based; 0 -> -1 dropped
            unsigned m = __ballot_sync(0xffffffffu,
                                       ((unsigned)(id - lo)) < (unsigned)SEGW);
            while (m) {
                int j0 = __ffs(m) - 1; m &= m - 1;
                int j1 = m ? (__ffs(m) - 1) : -1; if (j1 >= 0) m &= m - 1;
                int s0 = __shfl_sync(0xffffffffu, id, j0) - lo;
                int s1 = __shfl_sync(0xffffffffu, id, j1 >= 0 ? j1 : j0) - lo;
                float v0 = buf[(t * 32 + j0) * C_ + lane];
                float v1 = (j1 >= 0) ? buf[(t * 32 + j1) * C_ + lane] : 0.f;
                float2 b0 = wbin[s0 * C_ + lane];          // LDS.64
                b0.x += v0; b0.y += (v0 != 0.f) ? 1.f : 0.f;
                wbin[s0 * C_ + lane] = b0;                 // STS.64
                if (j1 >= 0) {                             // same-thread smem ops are
                    float2 b1 = wbin[s1 * C_ + lane];      // in-order -> s0==s1 correct
                    b1.x += v1; b1.y += (v1 != 0.f) ? 1.f : 0.f;
                    wbin[s1 * C_ + lane] = b1;
                }
            }
        }
        __syncthreads();   // stage cur free for the g+2 prefetch
    }

    // Write this CTA's partials (own warp's bins -> no extra sync needed).
    const size_t ob = (size_t)blockIdx.x * S_ * C_;
    #pragma unroll
    for (int sgl = 0; sgl < SEGW; sgl++)
        g_part[ob + (lo + sgl) * C_ + lane] = wbin[sgl * C_ + lane];
}

// ---------------------------------------------------------------------------
// k_final: reduce the 37 per-batch CTA partials for each (b, s), divide.
// 4 warps split the chunk list, smem combine. Fixed order -> deterministic.
// 0/0 -> NaN matches the reference for empty segments.
// ---------------------------------------------------------------------------
__global__ void __launch_bounds__(128) k_final(float* __restrict__ out) {
    __shared__ float2 red[4][32];
    int bs = blockIdx.x, b = bs >> 8, s = bs & (S_ - 1);
    int lane = threadIdx.x & 31, w = threadIdx.x >> 5;

    float2 acc = make_float2(0.f, 0.f);
    for (int k = w; k < CPB_; k += 4) {
        size_t idx = ((size_t)(b * CPB_ + k) * S_ + s) * C_ + lane;
        float2 p = g_part[idx];
        acc.x += p.x; acc.y += p.y;
    }
    red[w][lane] = acc;
    __syncthreads();
    if (w == 0) {
        float sum = red[0][lane].x + red[1][lane].x + red[2][lane].x + red[3][lane].x;
        float cnt = red[0][lane].y + red[1][lane].y + red[2][lane].y + red[3][lane].y;
        out[((size_t)s * B_ + b) * C_ + lane] = sum / cnt;
    }
}

// ---------------------------------------------------------------------------
// d_in[0] = image_output [8,512,512,32] f32
// d_in[1] = slic_output  [8,512,512,1]  i32
// d_in[2] = n_segments (fixed 256, compiled in)
// d_out   = [256, 8, 32] f32
// ---------------------------------------------------------------------------
extern "C" void kernel_launch(void* const* d_in, const int* in_sizes, int n_in,
                              void* d_out, int out_size) {
    const float* img  = (const float*)d_in[0];
    const int*   slic = (const int*)d_in[1];
    float*       out  = (float*)d_out;

    const int smem_bytes = 65536 + 32768 + 1024;   // 99328 -> 2 CTAs/SM
    cudaFuncSetAttribute(k_accum, cudaFuncAttributeMaxDynamicSharedMemorySize, smem_bytes);

    k_accum<<<NCTA, TPB, smem_bytes>>>(img, slic);
    k_final<<<B_ * S_, 128>>>(out);
}

// round 10
// speedup vs baseline: 1.1407x; 1.1407x over previous
#include <cuda_runtime.h>

// Fixed problem shape: B=8, H=W=512, C=32, n_segments=256
#define B_    8
#define HW_   (512 * 512)
#define C_    32
#define S_    256
#define CPB_  38                  // CTAs per batch
#define NCTA  (B_ * CPB_)         // 304 = 2 x 152 SMs (GB300) -> one exact wave
#define CW    16                  // consumer warps
#define TPB   ((CW + 1) * 32)     // 544: 16 consumer warps + 1 producer warp
#define SEGW  (S_ / CW)           // 16 segments owned per consumer warp
#define BP    64                  // pixels per stage (8 KB image + 256 B ids)
#define UPB   (HW_ / BP)          // 4096 stage-units per batch
#define D     4                   // pipeline depth

#define IMG_BYTES (BP * C_ * 4)   // 8192
#define IDS_BYTES (BP * 4)        // 256
#define TX_BYTES  (IMG_BYTES + IDS_BYTES)

// Per-CTA partials (.x = sum, .y = count as float; counts << 2^24 -> exact).
// Fully overwritten every launch -> no zeroing, replay-safe, zero atomics.
__device__ float2 g_part[(size_t)NCTA * S_ * C_];   // ~19.9 MB

__device__ __forceinline__ unsigned smem_u32(const void* p) {
    return (unsigned)__cvta_generic_to_shared(p);
}
__device__ __forceinline__ void mbar_init(unsigned a, unsigned cnt) {
    asm volatile("mbarrier.init.shared.b64 [%0], %1;" :: "r"(a), "r"(cnt) : "memory");
}
__device__ __forceinline__ void mbar_expect_tx(unsigned a, unsigned tx) {
    asm volatile("mbarrier.arrive.expect_tx.shared.b64 _, [%0], %1;" :: "r"(a), "r"(tx) : "memory");
}
__device__ __forceinline__ void mbar_arrive(unsigned a) {
    asm volatile("mbarrier.arrive.shared.b64 _, [%0];" :: "r"(a) : "memory");
}
__device__ __forceinline__ void mbar_wait_acq(unsigned a, unsigned ph) {
    asm volatile(
        "{\n\t.reg .pred P;\n\t"
        "WL%=:\n\tmbarrier.try_wait.parity.acquire.cta.shared::cta.b64 P, [%0], %1, 0x989680;\n\t"
        "@P bra WD%=;\n\tbra WL%=;\n\tWD%=:\n\t}"
        :: "r"(a), "r"(ph) : "memory");
}
__device__ __forceinline__ void mbar_wait_rlx(unsigned a, unsigned ph) {
    asm volatile(
        "{\n\t.reg .pred P;\n\t"
        "WL%=:\n\tmbarrier.try_wait.parity.relaxed.cta.shared::cta.b64 P, [%0], %1, 0x989680;\n\t"
        "@P bra WD%=;\n\tbra WL%=;\n\tWD%=:\n\t}"
        :: "r"(a), "r"(ph) : "memory");
}
__device__ __forceinline__ void bulk_g2s(unsigned dst, const void* src,
                                         unsigned bytes, unsigned mbar) {
    asm volatile(
        "cp.async.bulk.shared::cta.global.mbarrier::complete_tx::bytes [%0], [%1], %2, [%3];"
        :: "r"(dst), "l"(src), "r"(bytes), "r"(mbar) : "memory");
}

// ---------------------------------------------------------------------------
// k_accum: warp-specialized mbarrier pipeline. Producer warp streams the image
// sequentially via cp.async.bulk into a depth-4 stage ring; 16 consumer warps
// accumulate into warp-private float2 smem bins (no atomics, no __syncthreads
// in the loop). smem: bins 64 KB + 4 x (8 KB + 256 B) stages + barriers
// = ~97 KB -> 2 CTAs/SM, full 304-CTA wave resident.
// ---------------------------------------------------------------------------
__global__ void __launch_bounds__(TPB, 2) k_accum(const float* __restrict__ img,
                                                  const int* __restrict__ slic) {
    extern __shared__ char smem[];
    float2* s_bin = (float2*)smem;                               // 65536 B
    float*  s_buf = (float*)(smem + 65536);                      // D*8192 = 32768 B
    int*    s_ids = (int*)(smem + 65536 + 32768);                // D*256  = 1024 B
    // mbarriers: full[0..D-1] then empty[0..D-1], 8 B each
    const unsigned mbase = smem_u32(smem + 65536 + 32768 + 1024);

    const int tid = threadIdx.x, w = tid >> 5, lane = tid & 31;

    #pragma unroll
    for (int i = tid; i < S_ * C_; i += TPB) s_bin[i] = make_float2(0.f, 0.f);
    if (tid == 0) {
        #pragma unroll
        for (int i = 0; i < D; i++) {
            mbar_init(mbase + i * 8, 1);            // full: producer expect_tx
            mbar_init(mbase + (D + i) * 8, CW);     // empty: one arrive per consumer warp
        }
    }
    __syncthreads();

    // Per-batch contiguous unit range (107 or 108 units), never straddles batch.
    const int batch = blockIdx.x / CPB_;
    const int c     = blockIdx.x % CPB_;
    const int u0 = batch * UPB + (c * UPB) / CPB_;
    const int nb = batch * UPB + ((c + 1) * UPB) / CPB_ - u0;

    if (w == CW) {
        // ----- producer warp (lane 0 only) -----
        if (lane == 0) {
            int st = 0, ph = 1;                     // phase 1: first D waits pass free
            for (int g = 0; g < nb; g++) {
                mbar_wait_rlx(mbase + (D + st) * 8, (unsigned)ph);
                unsigned fb = mbase + st * 8;
                mbar_expect_tx(fb, TX_BYTES);
                bulk_g2s(smem_u32(s_buf + st * BP * C_),
                         img + (size_t)(u0 + g) * BP * C_, IMG_BYTES, fb);
                bulk_g2s(smem_u32(s_ids + st * BP),
                         slic + (size_t)(u0 + g) * BP, IDS_BYTES, fb);
                if (++st == D) { st = 0; ph ^= 1; }
            }
        }
    } else {
        // ----- consumer warps -----
        const int lo = w * SEGW;
        float2* wbin = s_bin + lo * C_;
        int st = 0, ph = 0;

        for (int g = 0; g < nb; g++) {
            mbar_wait_acq(mbase + st * 8, (unsigned)ph);
            const float* buf = s_buf + st * BP * C_;
            const int*   ids = s_ids + st * BP;

            #pragma unroll
            for (int t = 0; t < BP / 32; t++) {
                int id = ids[t * 32 + lane] - 1;               // 1-based; 0 -> -1 dropped
                unsigned m = __ballot_sync(0xffffffffu,
                                           ((unsigned)(id - lo)) < (unsigned)SEGW);
                while (m) {
                    int j0 = __ffs(m) - 1; m &= m - 1;
                    int j1 = m ? (__ffs(m) - 1) : -1; if (j1 >= 0) m &= m - 1;
                    int s0 = __shfl_sync(0xffffffffu, id, j0) - lo;
                    int s1 = __shfl_sync(0xffffffffu, id, j1 >= 0 ? j1 : j0) - lo;
                    float v0 = buf[(t * 32 + j0) * C_ + lane];
                    float v1 = (j1 >= 0) ? buf[(t * 32 + j1) * C_ + lane] : 0.f;
                    float2 b0 = wbin[s0 * C_ + lane];          // LDS.64
                    b0.x += v0; b0.y += (v0 != 0.f) ? 1.f : 0.f;
                    wbin[s0 * C_ + lane] = b0;                 // STS.64
                    if (j1 >= 0) {                             // same-thread smem ops are
                        float2 b1 = wbin[s1 * C_ + lane];      // in-order -> s0==s1 correct
                        b1.x += v1; b1.y += (v1 != 0.f) ? 1.f : 0.f;
                        wbin[s1 * C_ + lane] = b1;
                    }
                }
            }
            if (lane == 0) mbar_arrive(mbase + (D + st) * 8);  // release: orders reads
            if (++st == D) { st = 0; ph ^= 1; }
        }

        // Write this warp's partials (own bins -> no sync needed).
        const size_t ob = (size_t)blockIdx.x * S_ * C_;
        #pragma unroll
        for (int sgl = 0; sgl < SEGW; sgl++)
            g_part[ob + (lo + sgl) * C_ + lane] = wbin[sgl * C_ + lane];
    }
}

// ---------------------------------------------------------------------------
// k_final: reduce the 38 per-batch CTA partials for each (b, s), divide.
// 8 warps split the chunk list (MLP ~5 independent 256B loads per warp),
// smem combine in fixed order -> deterministic. 0/0 -> NaN matches reference.
// ---------------------------------------------------------------------------
__global__ void __launch_bounds__(256) k_final(float* __restrict__ out) {
    __shared__ float2 red[8][32];
    int bs = blockIdx.x, b = bs >> 8, s = bs & (S_ - 1);
    int lane = threadIdx.x & 31, w = threadIdx.x >> 5;

    float2 acc = make_float2(0.f, 0.f);
    #pragma unroll
    for (int k = w; k < CPB_; k += 8) {
        float2 p = g_part[((size_t)(b * CPB_ + k) * S_ + s) * C_ + lane];
        acc.x += p.x; acc.y += p.y;
    }
    red[w][lane] = acc;
    __syncthreads();
    if (w == 0) {
        float sum = 0.f, cnt = 0.f;
        #pragma unroll
        for (int i = 0; i < 8; i++) { sum += red[i][lane].x; cnt += red[i][lane].y; }
        out[((size_t)s * B_ + b) * C_ + lane] = sum / cnt;
    }
}

// ---------------------------------------------------------------------------
// d_in[0] = image_output [8,512,512,32] f32
// d_in[1] = slic_output  [8,512,512,1]  i32
// d_in[2] = n_segments (fixed 256, compiled in)
// d_out   = [256, 8, 32] f32
// ---------------------------------------------------------------------------
extern "C" void kernel_launch(void* const* d_in, const int* in_sizes, int n_in,
                              void* d_out, int out_size) {
    const float* img  = (const float*)d_in[0];
    const int*   slic = (const int*)d_in[1];
    float*       out  = (float*)d_out;

    const int smem_bytes = 65536 + 32768 + 1024 + 64;   // 99392 -> 2 CTAs/SM
    cudaFuncSetAttribute(k_accum, cudaFuncAttributeMaxDynamicSharedMemorySize, smem_bytes);

    k_accum<<<NCTA, TPB, smem_bytes>>>(img, slic);
    k_final<<<B_ * S_, 256>>>(out);
}